// round 5
// baseline (speedup 1.0000x reference)
#include <cuda_runtime.h>
#include <cuda_bf16.h>
#include <cstdint>

#define N_TRAIN 8192
#define M_PTS   8192
#define D_DIM   256
#define S_SPLIT 2
#define ROWS_PER_SPLIT (N_TRAIN / S_SPLIT)   // 4096
#define BM 64           // x_train rows per iteration (streamed)
#define BN 128          // x points per CTA (resident, output cols)
#define ITERS (ROWS_PER_SPLIT / BM)          // 64
#define NTHREADS 384    // 8 MMA warps + 4 epilogue warps

#define KC (1.4426950408889634f / 1024.0f)   // (1/sigma)^2 * log2(e)

// SMEM layout (bytes). bf16 tiles: row = 512B (256 bf16), 16B chunks XOR-swizzled
// by (chunk ^ (row&7)). D tiles: 64 rows x 128 fp32, natural row-major (512B rows).
#define OFF_B    0          // x tile (resident)          64KB
#define OFF_A0   65536      // x_train tile stage 0       32KB
#define OFF_A1   98304      // x_train tile stage 1       32KB
#define OFF_D0   131072     // dot tile stage 0           32KB
#define OFF_D1   163840     // dot tile stage 1           32KB
#define OFF_BAR  196608     // full0,full1,empty0,empty1 mbarriers (8B each)
#define SMEM_REQ 196736

__device__ __nv_bfloat16 g_A[(size_t)N_TRAIN * D_DIM];   // x_train bf16
__device__ __nv_bfloat16 g_Bm[(size_t)M_PTS * D_DIM];    // x bf16
__device__ float2 g_wn2[N_TRAIN];                        // {alpha*y, KC*||xt||^2}
__device__ float  g_km2[M_PTS];                          // KC*||x||^2
__device__ float  g_part[S_SPLIT * M_PTS];

// ---------------------------------------------------------------- helpers
__device__ __forceinline__ uint32_t smem_u32(const void* p) {
    uint32_t a;
    asm("{ .reg .u64 t; cvta.to.shared.u64 t, %1; cvt.u32.u64 %0, t; }"
        : "=r"(a) : "l"(p));
    return a;
}

__device__ __forceinline__ void mma16816(float* c, const uint32_t* a,
                                         uint32_t b0, uint32_t b1) {
    asm volatile(
        "mma.sync.aligned.m16n8k16.row.col.f32.bf16.bf16.f32 "
        "{%0,%1,%2,%3}, {%4,%5,%6,%7}, {%8,%9}, {%0,%1,%2,%3};\n"
        : "+f"(c[0]), "+f"(c[1]), "+f"(c[2]), "+f"(c[3])
        : "r"(a[0]), "r"(a[1]), "r"(a[2]), "r"(a[3]), "r"(b0), "r"(b1));
}

#define LDSM_X4(r0, r1, r2, r3, addr)                                        \
    asm volatile("ldmatrix.sync.aligned.m8n8.x4.shared.b16 {%0,%1,%2,%3}, [%4];" \
                 : "=r"(r0), "=r"(r1), "=r"(r2), "=r"(r3) : "r"(addr))

#define MBARRIER_INIT(mbar, cnt) \
    asm volatile("mbarrier.init.shared.b64 [%0], %1;" :: "r"(mbar), "r"((uint32_t)(cnt)) : "memory")
#define MBARRIER_ARRIVE(mbar) \
    asm volatile("mbarrier.arrive.shared.b64 _, [%0];" :: "r"(mbar) : "memory")

#define MBARRIER_WAIT_PARITY(mbar, parity) do {                                   \
    uint32_t _m = (mbar), _p = (uint32_t)(parity);                                \
    asm volatile(                                                                 \
        "{\n\t.reg .pred P1;\n\t"                                                 \
        "WAIT_LOOP_%=:\n\t"                                                       \
        "mbarrier.try_wait.parity.acquire.cta.shared::cta.b64 P1, [%0], %1, 0x989680;\n\t" \
        "@P1 bra.uni WAIT_DONE_%=;\n\t"                                           \
        "bra.uni WAIT_LOOP_%=;\n\t"                                               \
        "WAIT_DONE_%=:\n\t}"                                                      \
        :: "r"(_m), "r"(_p) : "memory");                                          \
} while (0)

// ROWS x 256 bf16 tile -> swizzled SMEM via cp.async (256 producer threads)
template <int ROWS>
__device__ __forceinline__ void cp_tile(uint32_t dst, const __nv_bfloat16* src, int tid) {
    const char* g = (const char*)src;
#pragma unroll
    for (int j = 0; j < (ROWS * 32) / 256; j++) {
        int idx = tid + j * 256;                      // 16B chunks
        int row = idx >> 5;
        int ch  = idx & 31;
        uint32_t so = dst + (uint32_t)row * 512 + (uint32_t)((ch ^ (row & 7)) << 4);
        asm volatile("cp.async.cg.shared.global [%0], [%1], 16;"
                     :: "r"(so), "l"(g + (size_t)idx * 16) : "memory");
    }
}

// ---------------------------------------------------------------- prep
__global__ void __launch_bounds__(256) prep_kernel(const float* __restrict__ xt,
                                                   const float* __restrict__ yt,
                                                   const float* __restrict__ al,
                                                   const float* __restrict__ x) {
    int w    = blockIdx.x * 8 + (threadIdx.x >> 5);
    int lane = threadIdx.x & 31;
    bool isA = (w < N_TRAIN);
    const float* src = isA ? xt + (size_t)w * D_DIM
                           : x + (size_t)(w - N_TRAIN) * D_DIM;
    __nv_bfloat16* dst = isA ? g_A + (size_t)w * D_DIM
                             : g_Bm + (size_t)(w - N_TRAIN) * D_DIM;
    float ss = 0.f;
#pragma unroll
    for (int j = 0; j < 2; j++) {
        float4 v = ((const float4*)src)[lane + 32 * j];
        __nv_bfloat16 h0 = __float2bfloat16(v.x), h1 = __float2bfloat16(v.y);
        __nv_bfloat16 h2 = __float2bfloat16(v.z), h3 = __float2bfloat16(v.w);
        float a0 = __bfloat162float(h0), a1 = __bfloat162float(h1);
        float a2 = __bfloat162float(h2), a3 = __bfloat162float(h3);
        ss += a0 * a0 + a1 * a1 + a2 * a2 + a3 * a3;
        uint2 u;
        u.x = (uint32_t)__bfloat16_as_ushort(h0) | ((uint32_t)__bfloat16_as_ushort(h1) << 16);
        u.y = (uint32_t)__bfloat16_as_ushort(h2) | ((uint32_t)__bfloat16_as_ushort(h3) << 16);
        ((uint2*)dst)[lane + 32 * j] = u;
    }
#pragma unroll
    for (int o = 16; o > 0; o >>= 1) ss += __shfl_xor_sync(0xffffffffu, ss, o);
    if (lane == 0) {
        if (isA) g_wn2[w] = make_float2(al[w] * yt[w], ss * KC);
        else     g_km2[w - N_TRAIN] = ss * KC;
    }
}

// ---------------------------------------------------------------- main
extern "C" __global__ void __launch_bounds__(NTHREADS, 1) svm_main_kernel() {
    extern __shared__ char smem_raw[];
    const uint32_t s_base = smem_u32(smem_raw);
    const uint32_t sB_u   = s_base + OFF_B;
    const uint32_t sA_u[2] = { s_base + OFF_A0, s_base + OFF_A1 };
    const uint32_t sD_u[2] = { s_base + OFF_D0, s_base + OFF_D1 };
    const uint32_t full_u[2]  = { s_base + OFF_BAR,      s_base + OFF_BAR + 8  };
    const uint32_t empty_u[2] = { s_base + OFF_BAR + 16, s_base + OFF_BAR + 24 };

    const int tid  = threadIdx.x;
    const int lane = tid & 31;
    const int wid  = tid >> 5;
    const int m0   = blockIdx.x * BN;               // x-point base (cols)
    const int n0   = blockIdx.y * ROWS_PER_SPLIT;   // x_train base (rows)

    if (tid == 0) {
        MBARRIER_INIT(full_u[0], 256); MBARRIER_INIT(full_u[1], 256);
        MBARRIER_INIT(empty_u[0], 128); MBARRIER_INIT(empty_u[1], 128);
    }
    __syncthreads();

    if (wid < 8) {
        // ================= PRODUCER: 8 MMA warps (256 threads) =================
        const int wr = wid >> 2;       // 0..1 : 32-row band
        const int wc = wid & 3;        // 0..3 : 32-col band

        // prologue: resident B tile + A stage 0
        cp_tile<BN>(sB_u, g_Bm + (size_t)m0 * D_DIM, tid);
        cp_tile<BM>(sA_u[0], g_A + (size_t)n0 * D_DIM, tid);
        asm volatile("cp.async.commit_group;");
        asm volatile("cp.async.wait_group 0;");
        asm volatile("bar.sync 1, 256;");

        const uint32_t aro  = (uint32_t)(wr * 32 + (lane & 15)) * 512;
        const uint32_t bro  = (uint32_t)(wc * 32 + (lane & 15)) * 512;
        const uint32_t csel = (uint32_t)(lane >> 4) & 1u;
        const uint32_t xr7  = (uint32_t)(lane & 7);
        int pe = 1;   // producer empty-phase: first waits pass immediately

        for (int i = 0; i < ITERS; i++) {
            const int s = i & 1;

            // prefetch next A stage (overlaps the whole iteration body)
            if (i + 1 < ITERS)
                cp_tile<BM>(sA_u[s ^ 1], g_A + (size_t)(n0 + (i + 1) * BM) * D_DIM, tid);
            asm volatile("cp.async.commit_group;");

            // ---- GEMM: 64x128x256 tile ----
            float acc[2][4][4];
#pragma unroll
            for (int mf = 0; mf < 2; mf++)
#pragma unroll
                for (int ng = 0; ng < 4; ng++)
#pragma unroll
                    for (int q = 0; q < 4; q++) acc[mf][ng][q] = 0.f;

            const uint32_t aB = sA_u[s] + aro;
            const uint32_t bB = sB_u + bro;
#pragma unroll
            for (int ks = 0; ks < 16; ks++) {
                const uint32_t coff = (((2u * ks + csel) ^ xr7) << 4);
                uint32_t a[2][4], bq[2][4];
#pragma unroll
                for (int mf = 0; mf < 2; mf++)
                    LDSM_X4(a[mf][0], a[mf][1], a[mf][2], a[mf][3], aB + mf * 8192 + coff);
#pragma unroll
                for (int p = 0; p < 2; p++)
                    LDSM_X4(bq[p][0], bq[p][1], bq[p][2], bq[p][3], bB + p * 8192 + coff);
#pragma unroll
                for (int mf = 0; mf < 2; mf++)
#pragma unroll
                    for (int ng = 0; ng < 4; ng++)
                        mma16816(acc[mf][ng], a[mf],
                                 bq[ng >> 1][ng & 1], bq[ng >> 1][(ng & 1) + 2]);
            }

            // ---- hand off: wait D stage free, store fp32 dots, signal full ----
            MBARRIER_WAIT_PARITY(empty_u[s], pe);
            const uint32_t dD = sD_u[s];
#pragma unroll
            for (int mf = 0; mf < 2; mf++)
#pragma unroll
                for (int ng = 0; ng < 4; ng++)
#pragma unroll
                    for (int rh = 0; rh < 2; rh++) {
                        uint32_t row = (uint32_t)(wr * 32 + mf * 16 + rh * 8 + (lane >> 2));
                        uint32_t col = (uint32_t)(wc * 32 + ng * 8 + (lane & 3) * 2);
                        asm volatile("st.shared.v2.f32 [%0], {%1,%2};"
                                     :: "r"(dD + row * 512 + col * 4),
                                        "f"(acc[mf][ng][rh * 2]), "f"(acc[mf][ng][rh * 2 + 1])
                                     : "memory");
                    }
            MBARRIER_ARRIVE(full_u[s]);

            asm volatile("cp.async.wait_group 0;");
            asm volatile("bar.sync 1, 256;");
            if (s == 1) pe ^= 1;
        }
    } else {
        // ================= CONSUMER: 4 epilogue warps (128 threads) =================
        const int col = (wid - 8) * 32 + lane;            // output column owned
        const float km2c = __ldg(&g_km2[m0 + col]);
        const float k2x = 2.f * KC;
        float colacc = 0.f;
        int pf = 0;

        for (int i = 0; i < ITERS; i++) {
            const int s = i & 1;
            // preload this iteration's {w, kn2} rows (lane r holds rows r, r+32)
            const float2* wp = g_wn2 + n0 + i * BM;
            float2 wa = __ldg(&wp[lane]);
            float2 wb = __ldg(&wp[lane + 32]);

            MBARRIER_WAIT_PARITY(full_u[s], pf);
            const uint32_t dD = sD_u[s] + (uint32_t)col * 4;
#pragma unroll
            for (int r = 0; r < BM; r++) {
                float wj  = __shfl_sync(0xffffffffu, (r < 32) ? wa.x : wb.x, r & 31);
                float n2j = __shfl_sync(0xffffffffu, (r < 32) ? wa.y : wb.y, r & 31);
                float d;
                asm("ld.shared.f32 %0, [%1];" : "=f"(d) : "r"(dD + (uint32_t)r * 512));
                float arg = fmaf(d, k2x, -n2j) - km2c;
                arg = fminf(arg, 0.f);
                float e;
                asm("ex2.approx.ftz.f32 %0, %1;" : "=f"(e) : "f"(arg));
                colacc = fmaf(e, wj, colacc);
            }
            MBARRIER_ARRIVE(empty_u[s]);
            if (s == 1) pf ^= 1;
        }

        g_part[blockIdx.y * M_PTS + m0 + col] = colacc;
    }
}

// ---------------------------------------------------------------- reduce
__global__ void reduce_kernel(float* __restrict__ out) {
    int m = blockIdx.x * blockDim.x + threadIdx.x;
    if (m < M_PTS) out[m] = g_part[m] + g_part[M_PTS + m];
}

// ---------------------------------------------------------------- launch
extern "C" void kernel_launch(void* const* d_in, const int* in_sizes, int n_in,
                              void* d_out, int out_size) {
    const float* xt = (const float*)d_in[0];
    const float* yt = (const float*)d_in[1];
    const float* al = (const float*)d_in[2];
    const float* x  = (const float*)d_in[3];

    cudaFuncSetAttribute(svm_main_kernel,
                         cudaFuncAttributeMaxDynamicSharedMemorySize, SMEM_REQ);

    prep_kernel<<<(N_TRAIN + M_PTS) / 8, 256>>>(xt, yt, al, x);
    svm_main_kernel<<<dim3(M_PTS / BN, S_SPLIT), NTHREADS, SMEM_REQ>>>();
    reduce_kernel<<<(M_PTS + 255) / 256, 256>>>((float*)d_out);
}

// round 6
// speedup vs baseline: 1.2208x; 1.2208x over previous
#include <cuda_runtime.h>
#include <cuda_bf16.h>
#include <cstdint>

#define N_TRAIN 8192
#define M_PTS   8192
#define D_DIM   256
#define S_SPLIT 2
#define ROWS_PER_SPLIT (N_TRAIN / S_SPLIT)   // 4096
#define BM 128          // x_train rows per iteration (streamed)
#define BN 128          // x points per CTA (resident, output cols)
#define ITERS (ROWS_PER_SPLIT / BM)          // 32
#define NTHREADS 256

#define KC (1.4426950408889634f / 1024.0f)   // (1/sigma)^2 * log2(e)

// SMEM (bytes). bf16 tiles: row = 512B, 16B chunks XOR-swizzled (ch ^ (row&7)).
#define OFF_B   0           // x tile (resident)        64KB
#define OFF_A0  65536       // x_train stage 0          64KB
#define OFF_A1  131072      // x_train stage 1          64KB
#define OFF_RED 196608      // cross-warp reduce         1KB
#define SMEM_REQ 197632

__device__ __nv_bfloat16 g_A[(size_t)N_TRAIN * D_DIM];
__device__ __nv_bfloat16 g_Bm[(size_t)M_PTS * D_DIM];
__device__ float2 g_wn2[N_TRAIN];            // {alpha*y, KC*||xt||^2}
__device__ float  g_km2[M_PTS];              // KC*||x||^2
__device__ float  g_part[S_SPLIT * M_PTS];

// ---------------------------------------------------------------- helpers
__device__ __forceinline__ uint32_t smem_u32(const void* p) {
    uint32_t a;
    asm("{ .reg .u64 t; cvta.to.shared.u64 t, %1; cvt.u32.u64 %0, t; }"
        : "=r"(a) : "l"(p));
    return a;
}

__device__ __forceinline__ void mma16816(float* c, const uint32_t* a,
                                         uint32_t b0, uint32_t b1) {
    asm volatile(
        "mma.sync.aligned.m16n8k16.row.col.f32.bf16.bf16.f32 "
        "{%0,%1,%2,%3}, {%4,%5,%6,%7}, {%8,%9}, {%0,%1,%2,%3};\n"
        : "+f"(c[0]), "+f"(c[1]), "+f"(c[2]), "+f"(c[3])
        : "r"(a[0]), "r"(a[1]), "r"(a[2]), "r"(a[3]), "r"(b0), "r"(b1));
}

#define LDSM_X4(r0, r1, r2, r3, addr)                                        \
    asm volatile("ldmatrix.sync.aligned.m8n8.x4.shared.b16 {%0,%1,%2,%3}, [%4];" \
                 : "=r"(r0), "=r"(r1), "=r"(r2), "=r"(r3) : "r"(addr))

// 128x256 bf16 tile (64KB) -> swizzled SMEM via cp.async (256 threads)
__device__ __forceinline__ void cp_tile(uint32_t dst, const __nv_bfloat16* src, int tid) {
    const char* g = (const char*)src;
#pragma unroll
    for (int j = 0; j < 16; j++) {
        int idx = tid + j * NTHREADS;
        int row = idx >> 5;
        int ch  = idx & 31;
        uint32_t so = dst + (uint32_t)row * 512 + (uint32_t)((ch ^ (row & 7)) << 4);
        asm volatile("cp.async.cg.shared.global [%0], [%1], 16;"
                     :: "r"(so), "l"(g + (size_t)idx * 16) : "memory");
    }
}

// ---------------------------------------------------------------- prep
__global__ void __launch_bounds__(256) prep_kernel(const float* __restrict__ xt,
                                                   const float* __restrict__ yt,
                                                   const float* __restrict__ al,
                                                   const float* __restrict__ x) {
    int w    = blockIdx.x * 8 + (threadIdx.x >> 5);
    int lane = threadIdx.x & 31;
    bool isA = (w < N_TRAIN);
    const float* src = isA ? xt + (size_t)w * D_DIM
                           : x + (size_t)(w - N_TRAIN) * D_DIM;
    __nv_bfloat16* dst = isA ? g_A + (size_t)w * D_DIM
                             : g_Bm + (size_t)(w - N_TRAIN) * D_DIM;
    float ss = 0.f;
#pragma unroll
    for (int j = 0; j < 2; j++) {
        float4 v = ((const float4*)src)[lane + 32 * j];
        __nv_bfloat16 h0 = __float2bfloat16(v.x), h1 = __float2bfloat16(v.y);
        __nv_bfloat16 h2 = __float2bfloat16(v.z), h3 = __float2bfloat16(v.w);
        float a0 = __bfloat162float(h0), a1 = __bfloat162float(h1);
        float a2 = __bfloat162float(h2), a3 = __bfloat162float(h3);
        ss += a0 * a0 + a1 * a1 + a2 * a2 + a3 * a3;
        uint2 u;
        u.x = (uint32_t)__bfloat16_as_ushort(h0) | ((uint32_t)__bfloat16_as_ushort(h1) << 16);
        u.y = (uint32_t)__bfloat16_as_ushort(h2) | ((uint32_t)__bfloat16_as_ushort(h3) << 16);
        ((uint2*)dst)[lane + 32 * j] = u;
    }
#pragma unroll
    for (int o = 16; o > 0; o >>= 1) ss += __shfl_xor_sync(0xffffffffu, ss, o);
    if (lane == 0) {
        if (isA) g_wn2[w] = make_float2(al[w] * yt[w], ss * KC);
        else     g_km2[w - N_TRAIN] = ss * KC;
    }
}

// ---------------------------------------------------------------- fused tile op
// MMA for the current tile (into cur) interleaved with the exp-epilogue of the
// PREVIOUS tile (prev). 4 epilogue elements per ks-step; different pipes overlap.
template <bool EPI>
__device__ __forceinline__ void mma_epi_tile(
    float (&cur)[4][4][4], float (&prev)[4][4][4],
    uint32_t aB, uint32_t bB, uint32_t csel, uint32_t xr7,
    const float2* __restrict__ wprev,   // g_wn2 rows of the PREVIOUS tile
    const float* km2v, float* colacc,
    int wr, int lane, float k2x)
{
    float2 w2[8];
    if (EPI) {
#pragma unroll
        for (int mf = 0; mf < 4; mf++)
#pragma unroll
            for (int rh = 0; rh < 2; rh++)
                w2[mf * 2 + rh] = __ldg(&wprev[wr * 64 + mf * 16 + rh * 8 + (lane >> 2)]);
    }
#pragma unroll
    for (int mf = 0; mf < 4; mf++)
#pragma unroll
        for (int ng = 0; ng < 4; ng++)
#pragma unroll
            for (int q = 0; q < 4; q++) cur[mf][ng][q] = 0.f;

#pragma unroll
    for (int ks = 0; ks < 16; ks++) {
        const uint32_t coff = (((2u * ks + csel) ^ xr7) << 4);
        uint32_t a[4][4], bq[2][4];
#pragma unroll
        for (int mf = 0; mf < 4; mf++)
            LDSM_X4(a[mf][0], a[mf][1], a[mf][2], a[mf][3], aB + mf * 8192 + coff);
#pragma unroll
        for (int p = 0; p < 2; p++)
            LDSM_X4(bq[p][0], bq[p][1], bq[p][2], bq[p][3], bB + p * 8192 + coff);
#pragma unroll
        for (int mf = 0; mf < 4; mf++)
#pragma unroll
            for (int ng = 0; ng < 4; ng++)
                mma16816(cur[mf][ng], a[mf],
                         bq[ng >> 1][ng & 1], bq[ng >> 1][(ng & 1) + 2]);
        if (EPI) {
#pragma unroll
            for (int q = 0; q < 4; q++) {
                const int e  = ks * 4 + q;          // e bits: [5:4]=mf [3:2]=ng [1]=rh [0]=h
                const int mf = e >> 4, ng = (e >> 2) & 3, rh = (e >> 1) & 1, h = e & 1;
                float2 wn = w2[mf * 2 + rh];
                float d = prev[mf][ng][rh * 2 + h];
                float arg = fmaf(d, k2x, -wn.y) - km2v[ng * 2 + h];
                arg = fminf(arg, 0.f);
                float ev;
                asm("ex2.approx.ftz.f32 %0, %1;" : "=f"(ev) : "f"(arg));
                colacc[ng * 2 + h] = fmaf(ev, wn.x, colacc[ng * 2 + h]);
            }
        }
    }
}

// standalone epilogue for the final tile
__device__ __forceinline__ void epi_only(
    float (&prev)[4][4][4], const float2* __restrict__ wprev,
    const float* km2v, float* colacc, int wr, int lane, float k2x)
{
#pragma unroll
    for (int mf = 0; mf < 4; mf++)
#pragma unroll
        for (int rh = 0; rh < 2; rh++) {
            float2 wn = __ldg(&wprev[wr * 64 + mf * 16 + rh * 8 + (lane >> 2)]);
#pragma unroll
            for (int ng = 0; ng < 4; ng++)
#pragma unroll
                for (int h = 0; h < 2; h++) {
                    float d = prev[mf][ng][rh * 2 + h];
                    float arg = fmaf(d, k2x, -wn.y) - km2v[ng * 2 + h];
                    arg = fminf(arg, 0.f);
                    float ev;
                    asm("ex2.approx.ftz.f32 %0, %1;" : "=f"(ev) : "f"(arg));
                    colacc[ng * 2 + h] = fmaf(ev, wn.x, colacc[ng * 2 + h]);
                }
        }
}

// ---------------------------------------------------------------- main
extern "C" __global__ void __launch_bounds__(NTHREADS, 1) svm_main_kernel() {
    extern __shared__ char smem_raw[];
    const uint32_t s_base = smem_u32(smem_raw);
    const uint32_t sB_u   = s_base + OFF_B;
    const uint32_t sA_u[2] = { s_base + OFF_A0, s_base + OFF_A1 };
    float* sRed = (float*)(smem_raw + OFF_RED);

    const int tid  = threadIdx.x;
    const int lane = tid & 31;
    const int wid  = tid >> 5;
    const int wr   = wid >> 2;     // 0..1 : 64-row band
    const int wc   = wid & 3;      // 0..3 : 32-col band
    const int m0   = blockIdx.x * BN;
    const int n0   = blockIdx.y * ROWS_PER_SPLIT;

    float km2v[8];
#pragma unroll
    for (int nf = 0; nf < 4; nf++)
#pragma unroll
        for (int h = 0; h < 2; h++)
            km2v[nf * 2 + h] = __ldg(&g_km2[m0 + wc * 32 + nf * 8 + (lane & 3) * 2 + h]);

    // prologue: resident B + A stage 0
    cp_tile(sB_u, g_Bm + (size_t)m0 * D_DIM, tid);
    cp_tile(sA_u[0], g_A + (size_t)n0 * D_DIM, tid);
    asm volatile("cp.async.commit_group;");
    asm volatile("cp.async.wait_group 0;");
    __syncthreads();

    const uint32_t aro  = (uint32_t)(wr * 64 + (lane & 15)) * 512;
    const uint32_t bro  = (uint32_t)(wc * 32 + (lane & 15)) * 512;
    const uint32_t csel = (uint32_t)(lane >> 4) & 1u;
    const uint32_t xr7  = (uint32_t)(lane & 7);
    const uint32_t bB   = sB_u + bro;
    const float2* wbase = g_wn2 + n0;

    float colacc[8];
#pragma unroll
    for (int j = 0; j < 8; j++) colacc[j] = 0.f;
    const float k2x = 2.f * KC;

    float accA[4][4][4], accB[4][4][4];

    // ---- iter 0: MMA only (no previous tile), prefetch stage 1 ----
    cp_tile(sA_u[1], g_A + (size_t)(n0 + BM) * D_DIM, tid);
    asm volatile("cp.async.commit_group;");
    mma_epi_tile<false>(accA, accB, sA_u[0] + aro, bB, csel, xr7,
                        wbase, km2v, colacc, wr, lane, k2x);
    asm volatile("cp.async.wait_group 0;");
    __syncthreads();

    // ---- pairs: i=1..ITERS-2 ----
#pragma unroll 1
    for (int ip = 1; ip < ITERS - 1; ip += 2) {
        // step ip (odd): MMA->accB from stage 1, epilogue accA (tile ip-1)
        cp_tile(sA_u[0], g_A + (size_t)(n0 + (ip + 1) * BM) * D_DIM, tid);
        asm volatile("cp.async.commit_group;");
        mma_epi_tile<true>(accB, accA, sA_u[1] + aro, bB, csel, xr7,
                           wbase + (ip - 1) * BM, km2v, colacc, wr, lane, k2x);
        asm volatile("cp.async.wait_group 0;");
        __syncthreads();

        // step ip+1 (even): MMA->accA from stage 0, epilogue accB (tile ip)
        if (ip + 2 < ITERS)
            cp_tile(sA_u[1], g_A + (size_t)(n0 + (ip + 2) * BM) * D_DIM, tid);
        asm volatile("cp.async.commit_group;");
        mma_epi_tile<true>(accA, accB, sA_u[0] + aro, bB, csel, xr7,
                           wbase + ip * BM, km2v, colacc, wr, lane, k2x);
        asm volatile("cp.async.wait_group 0;");
        __syncthreads();
    }

    // ---- leftover i = ITERS-1 (odd): MMA->accB from stage 1, epi accA ----
    mma_epi_tile<true>(accB, accA, sA_u[1] + aro, bB, csel, xr7,
                       wbase + (ITERS - 2) * BM, km2v, colacc, wr, lane, k2x);
    // final epilogue of the last tile
    epi_only(accB, wbase + (ITERS - 1) * BM, km2v, colacc, wr, lane, k2x);

    // ---- deterministic column reduction ----
#pragma unroll
    for (int j = 0; j < 8; j++) {
        float v = colacc[j];
        v += __shfl_xor_sync(0xffffffffu, v, 4);
        v += __shfl_xor_sync(0xffffffffu, v, 8);
        v += __shfl_xor_sync(0xffffffffu, v, 16);
        colacc[j] = v;
    }
    if (lane < 4) {
#pragma unroll
        for (int j = 0; j < 8; j++) {
            int col = wc * 32 + (j >> 1) * 8 + lane * 2 + (j & 1);
            sRed[wr * BN + col] = colacc[j];
        }
    }
    __syncthreads();
    if (tid < BN) {
        float sv = sRed[tid] + sRed[BN + tid];
        g_part[blockIdx.y * M_PTS + m0 + tid] = sv;
    }
}

// ---------------------------------------------------------------- reduce
__global__ void reduce_kernel(float* __restrict__ out) {
    int m = blockIdx.x * blockDim.x + threadIdx.x;
    if (m < M_PTS) out[m] = g_part[m] + g_part[M_PTS + m];
}

// ---------------------------------------------------------------- launch
extern "C" void kernel_launch(void* const* d_in, const int* in_sizes, int n_in,
                              void* d_out, int out_size) {
    const float* xt = (const float*)d_in[0];
    const float* yt = (const float*)d_in[1];
    const float* al = (const float*)d_in[2];
    const float* x  = (const float*)d_in[3];

    cudaFuncSetAttribute(svm_main_kernel,
                         cudaFuncAttributeMaxDynamicSharedMemorySize, SMEM_REQ);

    prep_kernel<<<(N_TRAIN + M_PTS) / 8, 256>>>(xt, yt, al, x);
    svm_main_kernel<<<dim3(M_PTS / BN, S_SPLIT), NTHREADS, SMEM_REQ>>>();
    reduce_kernel<<<(M_PTS + 255) / 256, 256>>>((float*)d_out);
}